// round 7
// baseline (speedup 1.0000x reference)
#include <cuda_runtime.h>
#include <cstdint>

#define BATCH   2048
#define DMODEL  2048
#define DSTATE  16
#define DEVENT  32

// ---------------- scratch ----------------
__device__ float g_delta[BATCH * DMODEL];   // delta_safe
__device__ float g_pole [BATCH * DMODEL];   // event @ A_We.T
__device__ float g_Abase[DMODEL * DSTATE];  // -exp(clip(A_log,-3,1))
__device__ float g_Bt   [BATCH * DSTATE];
__device__ float g_Ct   [BATCH * DSTATE];

// ---------------- helpers ----------------
__device__ __forceinline__ void mma_tf32(float* c, const uint32_t* a, const uint32_t* b) {
    asm volatile(
        "mma.sync.aligned.m16n8k8.row.col.f32.tf32.tf32.f32 "
        "{%0,%1,%2,%3},{%4,%5,%6,%7},{%8,%9},{%0,%1,%2,%3};"
        : "+f"(c[0]), "+f"(c[1]), "+f"(c[2]), "+f"(c[3])
        : "r"(a[0]), "r"(a[1]), "r"(a[2]), "r"(a[3]), "r"(b[0]), "r"(b[1]));
}

__device__ __forceinline__ void cp16(float* dst, const float* src) {
    uint32_t d = (uint32_t)__cvta_generic_to_shared(dst);
    asm volatile("cp.async.cg.shared.global [%0],[%1],16;\n" :: "r"(d), "l"(src));
}
__device__ __forceinline__ void cp_commit() {
    asm volatile("cp.async.commit_group;\n");
}

// ---------------- kernel 1: A_base ----------------
__global__ void k_abase(const float* __restrict__ A_log) {
    int i = blockIdx.x * blockDim.x + threadIdx.x;
    if (i < DMODEL * DSTATE) {
        float a = A_log[i];
        a = fminf(fmaxf(a, -3.0f), 1.0f);
        g_Abase[i] = -__expf(a);
    }
}

// ---------------- kernel 2: pole = event @ A_We.T ----------
__global__ __launch_bounds__(256) void k_pole(const float* __restrict__ Ev,
                                              const float* __restrict__ A_We) {
    __shared__ float Es[32][33];
    __shared__ float Ws[128][33];
    int t  = threadIdx.x;
    int b0 = blockIdx.x * 32;
    int d0 = blockIdx.y * 128;

    {
        int idx = t;
        int r = idx >> 3, c4 = idx & 7;
        float4 v = *(const float4*)(Ev + (size_t)(b0 + r) * DEVENT + c4 * 4);
        Es[r][c4 * 4 + 0] = v.x; Es[r][c4 * 4 + 1] = v.y;
        Es[r][c4 * 4 + 2] = v.z; Es[r][c4 * 4 + 3] = v.w;
    }
#pragma unroll
    for (int i = 0; i < 4; ++i) {
        int idx = t + i * 256;
        int r = idx >> 3, c4 = idx & 7;
        float4 v = *(const float4*)(A_We + (size_t)(d0 + r) * DEVENT + c4 * 4);
        Ws[r][c4 * 4 + 0] = v.x; Ws[r][c4 * 4 + 1] = v.y;
        Ws[r][c4 * 4 + 2] = v.z; Ws[r][c4 * 4 + 3] = v.w;
    }
    __syncthreads();

    int d_sub = t & 127;
    int half  = t >> 7;
    for (int bs = half; bs < 32; bs += 2) {
        float acc = 0.0f;
#pragma unroll
        for (int e = 0; e < 32; ++e) acc += Es[bs][e] * Ws[d_sub][e];
        g_pole[(size_t)(b0 + bs) * DMODEL + d0 + d_sub] = acc;
    }
}

// ---------------- kernel 3: B_t, C_t (skinny GEMMs) ----------------------
__global__ __launch_bounds__(256) void k_small(
    const float* __restrict__ X, const float* __restrict__ Ev,
    const float* __restrict__ B_W1, const float* __restrict__ B_b1,
    const float* __restrict__ B_W2, const float* __restrict__ B_b2,
    const float* __restrict__ B_We, const float* __restrict__ C_W) {
    __shared__ float Xs[32][132];
    __shared__ float Ws[48][132];
    __shared__ float Hs[32][33];

    int t    = threadIdx.x;
    int b0   = blockIdx.x * 32;
    int row  = t >> 3;
    int tcol = t & 7;

    float accH[4] = {0, 0, 0, 0};
    float accC[2] = {0, 0};

    for (int kc = 0; kc < DMODEL; kc += 128) {
#pragma unroll
        for (int i = 0; i < 4; ++i) {
            int idx = t + i * 256;
            int r = idx >> 5, c4 = idx & 31;
            float4 v = *(const float4*)(X + (size_t)(b0 + r) * DMODEL + kc + c4 * 4);
            *(float4*)(&Xs[r][c4 * 4]) = v;
        }
#pragma unroll
        for (int i = 0; i < 6; ++i) {
            int idx = t + i * 256;
            int r = idx >> 5, c4 = idx & 31;
            const float* src = (r < 32)
                ? (B_W1 + (size_t)r * DMODEL + kc + c4 * 4)
                : (C_W + (size_t)(r - 32) * DMODEL + kc + c4 * 4);
            float4 v = *(const float4*)src;
            *(float4*)(&Ws[r][c4 * 4]) = v;
        }
        __syncthreads();
#pragma unroll 4
        for (int kk = 0; kk < 128; ++kk) {
            float xv = Xs[row][kk];
#pragma unroll
            for (int i = 0; i < 4; ++i) accH[i] += xv * Ws[tcol + 8 * i][kk];
#pragma unroll
            for (int i = 0; i < 2; ++i) accC[i] += xv * Ws[32 + tcol + 8 * i][kk];
        }
        __syncthreads();
    }

#pragma unroll
    for (int i = 0; i < 4; ++i) {
        int j = tcol + 8 * i;
        float z = accH[i] + B_b1[j];
        Hs[row][j] = z / (1.0f + __expf(-z));
    }
#pragma unroll
    for (int i = 0; i < 2; ++i) {
        int n = tcol + 8 * i;
        g_Ct[(size_t)(b0 + row) * DSTATE + n] = accC[i];
    }
    __syncthreads();

    for (int o = t; o < 32 * 16; o += 256) {
        int r = o >> 4, n = o & 15;
        float acc = B_b2[n];
#pragma unroll
        for (int j = 0; j < 32; ++j) acc += Hs[r][j] * B_W2[n * 32 + j];
#pragma unroll
        for (int e = 0; e < 32; ++e) acc += Ev[(size_t)(b0 + r) * DEVENT + e] * B_We[n * 32 + e];
        g_Bt[(size_t)(b0 + r) * DSTATE + n] = acc;
    }
}

// ---------------- kernel 4: delta GEMM, 3-stage cp.async + frag pipeline --
#define STG 4608  // 128*36 floats per operand per stage
#define NST 3

__global__ __launch_bounds__(256, 2) void k_gemm_delta(
    const float* __restrict__ X, const float* __restrict__ Wd,
    const float* __restrict__ Ev, const float* __restrict__ We,
    const float* __restrict__ bd) {
    extern __shared__ float smbuf[];
    float* As = smbuf;              // [3][128][36]
    float* Bs = smbuf + NST * STG;  // [3][128][36]

    const int tid  = threadIdx.x;
    const int row0 = blockIdx.y * 128;   // batch
    const int col0 = blockIdx.x * 128;   // d_model
    const int wid  = tid >> 5, lane = tid & 31;
    const int g    = lane >> 2, tg = lane & 3;
    const int wm0  = (wid & 1) * 64;
    const int wn0  = (wid >> 1) * 32;

    float acc[4][4][4];
#pragma unroll
    for (int mi = 0; mi < 4; ++mi)
#pragma unroll
        for (int ni = 0; ni < 4; ++ni)
#pragma unroll
            for (int r = 0; r < 4; ++r) acc[mi][ni][r] = 0.0f;

    auto load_tile = [&](int kt, int s) {
        const float *srcA, *srcB;
        int lda, ldb;
        if (kt < 64) {
            srcA = X  + (size_t)row0 * DMODEL + kt * 32; lda = DMODEL;
            srcB = Wd + (size_t)col0 * DMODEL + kt * 32; ldb = DMODEL;
        } else {
            srcA = Ev + (size_t)row0 * DEVENT; lda = DEVENT;
            srcB = We + (size_t)col0 * DEVENT; ldb = DEVENT;
        }
        float* as = As + s * STG;
        float* bs = Bs + s * STG;
#pragma unroll
        for (int i = 0; i < 4; ++i) {
            int idx = tid + i * 256;     // 1024 16B chunks per operand
            int m = idx >> 3, k4 = idx & 7;
            cp16(as + m * 36 + k4 * 4, srcA + (size_t)m * lda + k4 * 4);
            cp16(bs + m * 36 + k4 * 4, srcB + (size_t)m * ldb + k4 * 4);
        }
        cp_commit();
    };

    // prologue: stages 0,1 hold tiles 0,1
    load_tile(0, 0);
    load_tile(1, 1);

    int s_load = 2;   // stage for tile kt+2
    int s_comp = 0;   // stage for tile kt

    for (int kt = 0; kt < 65; ++kt) {
        if (kt + 2 <= 64) {
            load_tile(kt + 2, s_load);
            if (++s_load == NST) s_load = 0;
        }
        int rem = 64 - kt;
        if      (rem >= 2) asm volatile("cp.async.wait_group 2;\n");
        else if (rem == 1) asm volatile("cp.async.wait_group 1;\n");
        else               asm volatile("cp.async.wait_group 0;\n");
        __syncthreads();

        const float* as = As + s_comp * STG;
        const float* bs = Bs + s_comp * STG;
        if (++s_comp == NST) s_comp = 0;

        // fragment double-buffered ks loop
        uint32_t a0[4][4], a1[4][4];
        auto ldA = [&](int ks, uint32_t A[4][4]) {
            int k = ks * 8 + tg;
#pragma unroll
            for (int mi = 0; mi < 4; ++mi) {
                int m = wm0 + mi * 16;
                A[mi][0] = __float_as_uint(as[(m + g) * 36 + k]);
                A[mi][1] = __float_as_uint(as[(m + g + 8) * 36 + k]);
                A[mi][2] = __float_as_uint(as[(m + g) * 36 + k + 4]);
                A[mi][3] = __float_as_uint(as[(m + g + 8) * 36 + k + 4]);
            }
        };
        auto mmaStep = [&](int ks, uint32_t A[4][4]) {
            int k = ks * 8 + tg;
#pragma unroll
            for (int ni = 0; ni < 4; ++ni) {
                int n = wn0 + ni * 8 + g;
                uint32_t b[2];
                b[0] = __float_as_uint(bs[n * 36 + k]);
                b[1] = __float_as_uint(bs[n * 36 + k + 4]);
#pragma unroll
                for (int mi = 0; mi < 4; ++mi)
                    mma_tf32(acc[mi][ni], A[mi], b);
            }
        };

        ldA(0, a0);
        ldA(1, a1);
        mmaStep(0, a0);
        ldA(2, a0);
        mmaStep(1, a1);
        ldA(3, a1);
        mmaStep(2, a0);
        mmaStep(3, a1);

        __syncthreads();
    }

    // epilogue: delta_safe = min(softplus(z + bd), 2)
#pragma unroll
    for (int mi = 0; mi < 4; ++mi) {
        int rbase = row0 + wm0 + mi * 16 + g;
#pragma unroll
        for (int ni = 0; ni < 4; ++ni) {
            int cbase = col0 + wn0 + ni * 8 + tg * 2;
#pragma unroll
            for (int r = 0; r < 4; ++r) {
                int bb = rbase + (r >> 1) * 8;
                int dd = cbase + (r & 1);
                float z = acc[mi][ni][r] + __ldg(&bd[dd]);
                float sp = fmaxf(z, 0.0f) + __logf(1.0f + __expf(-fabsf(z)));
                g_delta[(size_t)bb * DMODEL + dd] = fminf(sp, 2.0f);
            }
        }
    }
}

// ---------------- kernel 5: state update, 1 thread per (b,d) pair ---------
__global__ __launch_bounds__(256) void k_state(
    const float* __restrict__ X, const float* __restrict__ Hprev,
    const float* __restrict__ Dv, float* __restrict__ Yout,
    float* __restrict__ Hout) {
    int pair = blockIdx.x * 256 + threadIdx.x;   // (b,d)
    int b    = pair >> 11;
    int d    = pair & 2047;

    float delta = g_delta[pair];
    float pole  = g_pole[pair];
    float xv    = X[pair];

    const float4* hp = (const float4*)Hprev   + (size_t)pair * 4;
    const float4* ab = (const float4*)g_Abase + d * 4;
    const float4* bt = (const float4*)g_Bt    + b * 4;
    const float4* ct = (const float4*)g_Ct    + b * 4;
    float4*       ho = (float4*)Hout          + (size_t)pair * 4;

    // batch the 4 state loads for MLP
    float4 h0 = hp[0], h1 = hp[1], h2 = hp[2], h3 = hp[3];
    float4 a0 = ab[0], a1 = ab[1], a2 = ab[2], a3 = ab[3];

    float dbx = delta * xv;
    float y   = 0.0f;

#pragma unroll
    for (int q = 0; q < 4; ++q) {
        float4 a4 = (q == 0) ? a0 : (q == 1) ? a1 : (q == 2) ? a2 : a3;
        float4 h4 = (q == 0) ? h0 : (q == 1) ? h1 : (q == 2) ? h2 : h3;
        float4 b4 = bt[q];
        float4 c4 = ct[q];
        float4 hv;
        hv.x = __expf(delta * (a4.x + pole)) * h4.x + dbx * b4.x;
        hv.y = __expf(delta * (a4.y + pole)) * h4.y + dbx * b4.y;
        hv.z = __expf(delta * (a4.z + pole)) * h4.z + dbx * b4.z;
        hv.w = __expf(delta * (a4.w + pole)) * h4.w + dbx * b4.w;
        ho[q] = hv;
        y += hv.x * c4.x + hv.y * c4.y + hv.z * c4.z + hv.w * c4.w;
    }

    Yout[pair] = y + Dv[d] * xv;
}

// ---------------- launch ----------------
extern "C" void kernel_launch(void* const* d_in, const int* in_sizes, int n_in,
                              void* d_out, int out_size) {
    const float* x      = (const float*)d_in[0];
    const float* h_prev = (const float*)d_in[1];
    const float* ev     = (const float*)d_in[2];
    const float* A_log  = (const float*)d_in[3];
    const float* Dv     = (const float*)d_in[4];
    const float* Wd     = (const float*)d_in[5];
    const float* bd     = (const float*)d_in[6];
    const float* We     = (const float*)d_in[7];
    const float* B_W1   = (const float*)d_in[8];
    const float* B_b1   = (const float*)d_in[9];
    const float* B_W2   = (const float*)d_in[10];
    const float* B_b2   = (const float*)d_in[11];
    const float* B_We   = (const float*)d_in[12];
    const float* A_We   = (const float*)d_in[13];
    const float* C_W    = (const float*)d_in[14];

    float* y_out = (float*)d_out;
    float* h_out = y_out + (size_t)BATCH * DMODEL;

    const int gemm_smem = 2 * NST * STG * (int)sizeof(float);  // 110592 B
    cudaFuncSetAttribute(k_gemm_delta,
                         cudaFuncAttributeMaxDynamicSharedMemorySize, gemm_smem);

    k_abase<<<(DMODEL * DSTATE + 255) / 256, 256>>>(A_log);
    k_pole<<<dim3(BATCH / 32, DMODEL / 128), 256>>>(ev, A_We);
    k_small<<<BATCH / 32, 256>>>(x, ev, B_W1, B_b1, B_W2, B_b2, B_We, C_W);
    k_gemm_delta<<<dim3(DMODEL / 128, BATCH / 128), 256, gemm_smem>>>(
        x, Wd, ev, We, bd);
    k_state<<<(BATCH * DMODEL) / 256, 256>>>(x, h_prev, Dv, y_out, h_out);
}

// round 8
// speedup vs baseline: 1.0312x; 1.0312x over previous
#include <cuda_runtime.h>
#include <cstdint>

#define BATCH   2048
#define DMODEL  2048
#define DSTATE  16
#define DEVENT  32

// ---------------- scratch ----------------
__device__ float g_delta[BATCH * DMODEL];   // delta_safe
__device__ float g_pole [BATCH * DMODEL];   // event @ A_We.T
__device__ float g_Abase[DMODEL * DSTATE];  // -exp(clip(A_log,-3,1))
__device__ float g_Bt   [BATCH * DSTATE];
__device__ float g_Ct   [BATCH * DSTATE];

// ---------------- helpers ----------------
__device__ __forceinline__ void mma_tf32(float* c, const uint32_t* a, const uint32_t* b) {
    asm volatile(
        "mma.sync.aligned.m16n8k8.row.col.f32.tf32.tf32.f32 "
        "{%0,%1,%2,%3},{%4,%5,%6,%7},{%8,%9},{%0,%1,%2,%3};"
        : "+f"(c[0]), "+f"(c[1]), "+f"(c[2]), "+f"(c[3])
        : "r"(a[0]), "r"(a[1]), "r"(a[2]), "r"(a[3]), "r"(b[0]), "r"(b[1]));
}

__device__ __forceinline__ void cp16(float* dst, const float* src) {
    uint32_t d = (uint32_t)__cvta_generic_to_shared(dst);
    asm volatile("cp.async.cg.shared.global [%0],[%1],16;\n" :: "r"(d), "l"(src));
}
__device__ __forceinline__ void cp_commit() {
    asm volatile("cp.async.commit_group;\n");
}

// ---------------- kernel 1: A_base ----------------
__global__ void k_abase(const float* __restrict__ A_log) {
    int i = blockIdx.x * blockDim.x + threadIdx.x;
    if (i < DMODEL * DSTATE) {
        float a = A_log[i];
        a = fminf(fmaxf(a, -3.0f), 1.0f);
        g_Abase[i] = -__expf(a);
    }
}

// ---------------- kernel 2: pole = event @ A_We.T ----------
__global__ __launch_bounds__(256) void k_pole(const float* __restrict__ Ev,
                                              const float* __restrict__ A_We) {
    __shared__ float Es[32][33];
    __shared__ float Ws[128][33];
    int t  = threadIdx.x;
    int b0 = blockIdx.x * 32;
    int d0 = blockIdx.y * 128;

    {
        int idx = t;
        int r = idx >> 3, c4 = idx & 7;
        float4 v = *(const float4*)(Ev + (size_t)(b0 + r) * DEVENT + c4 * 4);
        Es[r][c4 * 4 + 0] = v.x; Es[r][c4 * 4 + 1] = v.y;
        Es[r][c4 * 4 + 2] = v.z; Es[r][c4 * 4 + 3] = v.w;
    }
#pragma unroll
    for (int i = 0; i < 4; ++i) {
        int idx = t + i * 256;
        int r = idx >> 3, c4 = idx & 7;
        float4 v = *(const float4*)(A_We + (size_t)(d0 + r) * DEVENT + c4 * 4);
        Ws[r][c4 * 4 + 0] = v.x; Ws[r][c4 * 4 + 1] = v.y;
        Ws[r][c4 * 4 + 2] = v.z; Ws[r][c4 * 4 + 3] = v.w;
    }
    __syncthreads();

    int d_sub = t & 127;
    int half  = t >> 7;
    for (int bs = half; bs < 32; bs += 2) {
        float acc = 0.0f;
#pragma unroll
        for (int e = 0; e < 32; ++e) acc += Es[bs][e] * Ws[d_sub][e];
        g_pole[(size_t)(b0 + bs) * DMODEL + d0 + d_sub] = acc;
    }
}

// ---------------- kernel 3: B_t, C_t (skinny GEMMs) ----------------------
__global__ __launch_bounds__(256) void k_small(
    const float* __restrict__ X, const float* __restrict__ Ev,
    const float* __restrict__ B_W1, const float* __restrict__ B_b1,
    const float* __restrict__ B_W2, const float* __restrict__ B_b2,
    const float* __restrict__ B_We, const float* __restrict__ C_W) {
    __shared__ float Xs[32][132];
    __shared__ float Ws[48][132];
    __shared__ float Hs[32][33];

    int t    = threadIdx.x;
    int b0   = blockIdx.x * 32;
    int row  = t >> 3;
    int tcol = t & 7;

    float accH[4] = {0, 0, 0, 0};
    float accC[2] = {0, 0};

    for (int kc = 0; kc < DMODEL; kc += 128) {
#pragma unroll
        for (int i = 0; i < 4; ++i) {
            int idx = t + i * 256;
            int r = idx >> 5, c4 = idx & 31;
            float4 v = *(const float4*)(X + (size_t)(b0 + r) * DMODEL + kc + c4 * 4);
            *(float4*)(&Xs[r][c4 * 4]) = v;
        }
#pragma unroll
        for (int i = 0; i < 6; ++i) {
            int idx = t + i * 256;
            int r = idx >> 5, c4 = idx & 31;
            const float* src = (r < 32)
                ? (B_W1 + (size_t)r * DMODEL + kc + c4 * 4)
                : (C_W + (size_t)(r - 32) * DMODEL + kc + c4 * 4);
            float4 v = *(const float4*)src;
            *(float4*)(&Ws[r][c4 * 4]) = v;
        }
        __syncthreads();
#pragma unroll 4
        for (int kk = 0; kk < 128; ++kk) {
            float xv = Xs[row][kk];
#pragma unroll
            for (int i = 0; i < 4; ++i) accH[i] += xv * Ws[tcol + 8 * i][kk];
#pragma unroll
            for (int i = 0; i < 2; ++i) accC[i] += xv * Ws[32 + tcol + 8 * i][kk];
        }
        __syncthreads();
    }

#pragma unroll
    for (int i = 0; i < 4; ++i) {
        int j = tcol + 8 * i;
        float z = accH[i] + B_b1[j];
        Hs[row][j] = z / (1.0f + __expf(-z));
    }
#pragma unroll
    for (int i = 0; i < 2; ++i) {
        int n = tcol + 8 * i;
        g_Ct[(size_t)(b0 + row) * DSTATE + n] = accC[i];
    }
    __syncthreads();

    for (int o = t; o < 32 * 16; o += 256) {
        int r = o >> 4, n = o & 15;
        float acc = B_b2[n];
#pragma unroll
        for (int j = 0; j < 32; ++j) acc += Hs[r][j] * B_W2[n * 32 + j];
#pragma unroll
        for (int e = 0; e < 32; ++e) acc += Ev[(size_t)(b0 + r) * DEVENT + e] * B_We[n * 32 + e];
        g_Bt[(size_t)(b0 + r) * DSTATE + n] = acc;
    }
}

// ---------------- kernel 4: delta GEMM, cp.async double-buffered ----------
#define STG 4608  // 128*36 floats per operand per stage

__global__ __launch_bounds__(256) void k_gemm_delta(
    const float* __restrict__ X, const float* __restrict__ Wd,
    const float* __restrict__ Ev, const float* __restrict__ We,
    const float* __restrict__ bd) {
    extern __shared__ float smbuf[];
    float* As = smbuf;            // [2][128][36]
    float* Bs = smbuf + 2 * STG;  // [2][128][36]

    const int tid  = threadIdx.x;
    const int row0 = blockIdx.y * 128;   // batch
    const int col0 = blockIdx.x * 128;   // d_model
    const int wid  = tid >> 5, lane = tid & 31;
    const int g    = lane >> 2, tg = lane & 3;
    const int wm0  = (wid & 1) * 64;
    const int wn0  = (wid >> 1) * 32;

    float acc[4][4][4];
#pragma unroll
    for (int mi = 0; mi < 4; ++mi)
#pragma unroll
        for (int ni = 0; ni < 4; ++ni)
#pragma unroll
            for (int r = 0; r < 4; ++r) acc[mi][ni][r] = 0.0f;

    auto load_tile = [&](int kt, int s) {
        const float *srcA, *srcB;
        int lda, ldb;
        if (kt < 64) {
            srcA = X  + (size_t)row0 * DMODEL + kt * 32; lda = DMODEL;
            srcB = Wd + (size_t)col0 * DMODEL + kt * 32; ldb = DMODEL;
        } else {
            srcA = Ev + (size_t)row0 * DEVENT; lda = DEVENT;
            srcB = We + (size_t)col0 * DEVENT; ldb = DEVENT;
        }
        float* as = As + s * STG;
        float* bs = Bs + s * STG;
#pragma unroll
        for (int i = 0; i < 4; ++i) {
            int idx = tid + i * 256;     // 1024 16B chunks per operand
            int m = idx >> 3, k4 = idx & 7;
            cp16(as + m * 36 + k4 * 4, srcA + (size_t)m * lda + k4 * 4);
            cp16(bs + m * 36 + k4 * 4, srcB + (size_t)m * ldb + k4 * 4);
        }
    };

    load_tile(0, 0);
    cp_commit();

    for (int kt = 0; kt < 65; ++kt) {
        if (kt < 64) {
            load_tile(kt + 1, (kt + 1) & 1);
            cp_commit();
            asm volatile("cp.async.wait_group 1;\n");
        } else {
            asm volatile("cp.async.wait_group 0;\n");
        }
        __syncthreads();

        const float* as = As + (kt & 1) * STG;
        const float* bs = Bs + (kt & 1) * STG;
#pragma unroll
        for (int ks = 0; ks < 4; ++ks) {
            uint32_t a[4][4], b[4][2];
            int k = ks * 8 + tg;
#pragma unroll
            for (int mi = 0; mi < 4; ++mi) {
                int m = wm0 + mi * 16;
                a[mi][0] = __float_as_uint(as[(m + g) * 36 + k]);
                a[mi][1] = __float_as_uint(as[(m + g + 8) * 36 + k]);
                a[mi][2] = __float_as_uint(as[(m + g) * 36 + k + 4]);
                a[mi][3] = __float_as_uint(as[(m + g + 8) * 36 + k + 4]);
            }
#pragma unroll
            for (int ni = 0; ni < 4; ++ni) {
                int n = wn0 + ni * 8 + g;
                b[ni][0] = __float_as_uint(bs[n * 36 + k]);
                b[ni][1] = __float_as_uint(bs[n * 36 + k + 4]);
            }
#pragma unroll
            for (int mi = 0; mi < 4; ++mi)
#pragma unroll
                for (int ni = 0; ni < 4; ++ni)
                    mma_tf32(acc[mi][ni], a[mi], b[ni]);
        }
        __syncthreads();
    }

    // epilogue: delta_safe = min(softplus(z + bd), 2)
#pragma unroll
    for (int mi = 0; mi < 4; ++mi) {
        int rbase = row0 + wm0 + mi * 16 + g;
#pragma unroll
        for (int ni = 0; ni < 4; ++ni) {
            int cbase = col0 + wn0 + ni * 8 + tg * 2;
#pragma unroll
            for (int r = 0; r < 4; ++r) {
                int bb = rbase + (r >> 1) * 8;
                int dd = cbase + (r & 1);
                float z = acc[mi][ni][r] + __ldg(&bd[dd]);
                float sp = fmaxf(z, 0.0f) + __logf(1.0f + __expf(-fabsf(z)));
                g_delta[(size_t)bb * DMODEL + dd] = fminf(sp, 2.0f);
            }
        }
    }
}

// ---------------- kernel 5: state update (R1 4-lane layout) ---------------
__global__ __launch_bounds__(256) void k_state(
    const float* __restrict__ X, const float* __restrict__ Hprev,
    const float* __restrict__ Dv, float* __restrict__ Yout,
    float* __restrict__ Hout) {
    int tid  = blockIdx.x * 256 + threadIdx.x;
    int pair = tid >> 2;          // (b,d)
    int q    = tid & 3;           // state quarter
    int b    = pair >> 11;
    int d    = pair & 2047;

    float delta = g_delta[pair];
    float pole  = g_pole[pair];
    float xv    = X[pair];

    float4 hp = ((const float4*)Hprev)[(size_t)pair * 4 + q];
    float4 ab = ((const float4*)g_Abase)[d * 4 + q];
    float4 bt = ((const float4*)g_Bt)[b * 4 + q];
    float4 ct = ((const float4*)g_Ct)[b * 4 + q];

    float dbx = delta * xv;
    float4 h;
    h.x = __expf(delta * (ab.x + pole)) * hp.x + dbx * bt.x;
    h.y = __expf(delta * (ab.y + pole)) * hp.y + dbx * bt.y;
    h.z = __expf(delta * (ab.z + pole)) * hp.z + dbx * bt.z;
    h.w = __expf(delta * (ab.w + pole)) * hp.w + dbx * bt.w;

    ((float4*)Hout)[(size_t)pair * 4 + q] = h;

    float partial = h.x * ct.x + h.y * ct.y + h.z * ct.z + h.w * ct.w;
    partial += __shfl_xor_sync(0xffffffff, partial, 1);
    partial += __shfl_xor_sync(0xffffffff, partial, 2);
    if (q == 0) Yout[pair] = partial + Dv[d] * xv;
}

// ---------------- launch: fork prep kernels parallel to the GEMM ----------
extern "C" void kernel_launch(void* const* d_in, const int* in_sizes, int n_in,
                              void* d_out, int out_size) {
    const float* x      = (const float*)d_in[0];
    const float* h_prev = (const float*)d_in[1];
    const float* ev     = (const float*)d_in[2];
    const float* A_log  = (const float*)d_in[3];
    const float* Dv     = (const float*)d_in[4];
    const float* Wd     = (const float*)d_in[5];
    const float* bd     = (const float*)d_in[6];
    const float* We     = (const float*)d_in[7];
    const float* B_W1   = (const float*)d_in[8];
    const float* B_b1   = (const float*)d_in[9];
    const float* B_W2   = (const float*)d_in[10];
    const float* B_b2   = (const float*)d_in[11];
    const float* B_We   = (const float*)d_in[12];
    const float* A_We   = (const float*)d_in[13];
    const float* C_W    = (const float*)d_in[14];

    float* y_out = (float*)d_out;
    float* h_out = y_out + (size_t)BATCH * DMODEL;

    // one-time host resources (no device memory involved)
    static cudaStream_t sB = nullptr;
    static cudaEvent_t  evFork = nullptr, evPrep = nullptr;
    if (sB == nullptr) {
        cudaStreamCreateWithFlags(&sB, cudaStreamNonBlocking);
        cudaEventCreateWithFlags(&evFork, cudaEventDisableTiming);
        cudaEventCreateWithFlags(&evPrep, cudaEventDisableTiming);
        cudaFuncSetAttribute(k_gemm_delta,
                             cudaFuncAttributeMaxDynamicSharedMemorySize,
                             4 * STG * (int)sizeof(float));
    }

    const int gemm_smem = 4 * STG * (int)sizeof(float);  // 73728 B

    // fork: side stream joins the (possibly capturing) default stream
    cudaEventRecord(evFork, 0);
    cudaStreamWaitEvent(sB, evFork, 0);

    // prep kernels on side stream (independent of GEMM)
    k_abase<<<(DMODEL * DSTATE + 255) / 256, 256, 0, sB>>>(A_log);
    k_pole<<<dim3(BATCH / 32, DMODEL / 128), 256, 0, sB>>>(ev, A_We);
    k_small<<<BATCH / 32, 256, 0, sB>>>(x, ev, B_W1, B_b1, B_W2, B_b2, B_We, C_W);
    cudaEventRecord(evPrep, sB);

    // GEMM on the main stream, concurrent with prep
    k_gemm_delta<<<dim3(DMODEL / 128, BATCH / 128), 256, gemm_smem>>>(
        x, Wd, ev, We, bd);

    // join: state needs both GEMM (main) and prep (side)
    cudaStreamWaitEvent(0, evPrep, 0);
    k_state<<<(BATCH * DMODEL * 4) / 256, 256>>>(x, h_prev, Dv, y_out, h_out);
}

// round 9
// speedup vs baseline: 1.2335x; 1.1962x over previous
#include <cuda_runtime.h>
#include <cstdint>

#define BATCH   2048
#define DMODEL  2048
#define DSTATE  16
#define DEVENT  32

// ---------------- scratch ----------------
__device__ float g_delta[BATCH * DMODEL];   // delta_safe
__device__ float g_pole [BATCH * DMODEL];   // event @ A_We.T
__device__ float g_Abase[DMODEL * DSTATE];  // -exp(clip(A_log,-3,1))
__device__ float g_Bt   [BATCH * DSTATE];
__device__ float g_Ct   [BATCH * DSTATE];
__device__ float g_partH[4][BATCH * 2 * DSTATE];  // split-K partials of x@B_W1.T
__device__ float g_partC[4][BATCH * DSTATE];      // split-K partials of x@C_W.T

// ---------------- helpers ----------------
__device__ __forceinline__ void mma_tf32(float* c, const uint32_t* a, const uint32_t* b) {
    asm volatile(
        "mma.sync.aligned.m16n8k8.row.col.f32.tf32.tf32.f32 "
        "{%0,%1,%2,%3},{%4,%5,%6,%7},{%8,%9},{%0,%1,%2,%3};"
        : "+f"(c[0]), "+f"(c[1]), "+f"(c[2]), "+f"(c[3])
        : "r"(a[0]), "r"(a[1]), "r"(a[2]), "r"(a[3]), "r"(b[0]), "r"(b[1]));
}

__device__ __forceinline__ void cp16(float* dst, const float* src) {
    uint32_t d = (uint32_t)__cvta_generic_to_shared(dst);
    asm volatile("cp.async.cg.shared.global [%0],[%1],16;\n" :: "r"(d), "l"(src));
}
__device__ __forceinline__ void cp_commit() {
    asm volatile("cp.async.commit_group;\n");
}

// ---------------- kernel 1: pole = event @ A_We.T (+ A_base fold) ---------
__global__ __launch_bounds__(256) void k_pole(const float* __restrict__ Ev,
                                              const float* __restrict__ A_We,
                                              const float* __restrict__ A_log) {
    __shared__ float Es[32][33];
    __shared__ float Ws[128][33];
    int t  = threadIdx.x;
    int b0 = blockIdx.x * 32;
    int d0 = blockIdx.y * 128;

    // folded A_base: 64 blocks (y==0) x 256 thr x 2 elems = 32768
    if (blockIdx.y == 0) {
        int i = (blockIdx.x * 256 + t) * 2;
#pragma unroll
        for (int e = 0; e < 2; ++e) {
            float a = A_log[i + e];
            a = fminf(fmaxf(a, -3.0f), 1.0f);
            g_Abase[i + e] = -__expf(a);
        }
    }

    {
        int idx = t;
        int r = idx >> 3, c4 = idx & 7;
        float4 v = *(const float4*)(Ev + (size_t)(b0 + r) * DEVENT + c4 * 4);
        Es[r][c4 * 4 + 0] = v.x; Es[r][c4 * 4 + 1] = v.y;
        Es[r][c4 * 4 + 2] = v.z; Es[r][c4 * 4 + 3] = v.w;
    }
#pragma unroll
    for (int i = 0; i < 4; ++i) {
        int idx = t + i * 256;
        int r = idx >> 3, c4 = idx & 7;
        float4 v = *(const float4*)(A_We + (size_t)(d0 + r) * DEVENT + c4 * 4);
        Ws[r][c4 * 4 + 0] = v.x; Ws[r][c4 * 4 + 1] = v.y;
        Ws[r][c4 * 4 + 2] = v.z; Ws[r][c4 * 4 + 3] = v.w;
    }
    __syncthreads();

    int d_sub = t & 127;
    int half  = t >> 7;
    for (int bs = half; bs < 32; bs += 2) {
        float acc = 0.0f;
#pragma unroll
        for (int e = 0; e < 32; ++e) acc += Es[bs][e] * Ws[d_sub][e];
        g_pole[(size_t)(b0 + bs) * DMODEL + d0 + d_sub] = acc;
    }
}

// ---------------- kernel 2a: split-K partials of x@B_W1.T and x@C_W.T -----
// grid (64 batch-tiles, 4 K-splits), 256 thr; each split covers K=512.
__global__ __launch_bounds__(256) void k_small_p(
    const float* __restrict__ X,
    const float* __restrict__ B_W1, const float* __restrict__ C_W) {
    __shared__ float Xs[32][132];
    __shared__ float Ws[48][132];

    int t    = threadIdx.x;
    int b0   = blockIdx.x * 32;
    int kb   = blockIdx.y * 512;
    int row  = t >> 3;
    int tcol = t & 7;

    float accH[4] = {0, 0, 0, 0};
    float accC[2] = {0, 0};

    for (int kc = kb; kc < kb + 512; kc += 128) {
#pragma unroll
        for (int i = 0; i < 4; ++i) {
            int idx = t + i * 256;
            int r = idx >> 5, c4 = idx & 31;
            float4 v = *(const float4*)(X + (size_t)(b0 + r) * DMODEL + kc + c4 * 4);
            *(float4*)(&Xs[r][c4 * 4]) = v;
        }
#pragma unroll
        for (int i = 0; i < 6; ++i) {
            int idx = t + i * 256;
            int r = idx >> 5, c4 = idx & 31;
            const float* src = (r < 32)
                ? (B_W1 + (size_t)r * DMODEL + kc + c4 * 4)
                : (C_W + (size_t)(r - 32) * DMODEL + kc + c4 * 4);
            float4 v = *(const float4*)src;
            *(float4*)(&Ws[r][c4 * 4]) = v;
        }
        __syncthreads();
#pragma unroll 4
        for (int kk = 0; kk < 128; ++kk) {
            float xv = Xs[row][kk];
#pragma unroll
            for (int i = 0; i < 4; ++i) accH[i] += xv * Ws[tcol + 8 * i][kk];
#pragma unroll
            for (int i = 0; i < 2; ++i) accC[i] += xv * Ws[32 + tcol + 8 * i][kk];
        }
        __syncthreads();
    }

    int ks = blockIdx.y;
#pragma unroll
    for (int i = 0; i < 4; ++i)
        g_partH[ks][(size_t)(b0 + row) * 32 + tcol + 8 * i] = accH[i];
#pragma unroll
    for (int i = 0; i < 2; ++i)
        g_partC[ks][(size_t)(b0 + row) * DSTATE + tcol + 8 * i] = accC[i];
}

// ---------------- kernel 2b: combine partials, silu, B_t / C_t ------------
__global__ __launch_bounds__(256) void k_small_f(
    const float* __restrict__ Ev,
    const float* __restrict__ B_b1, const float* __restrict__ B_W2,
    const float* __restrict__ B_b2, const float* __restrict__ B_We) {
    __shared__ float Hs[32][33];

    int t    = threadIdx.x;
    int b0   = blockIdx.x * 32;
    int row  = t >> 3;
    int tcol = t & 7;

#pragma unroll
    for (int i = 0; i < 4; ++i) {
        int j = tcol + 8 * i;
        size_t off = (size_t)(b0 + row) * 32 + j;
        float z = g_partH[0][off] + g_partH[1][off]
                + g_partH[2][off] + g_partH[3][off] + B_b1[j];
        Hs[row][j] = z / (1.0f + __expf(-z));
    }
#pragma unroll
    for (int i = 0; i < 2; ++i) {
        int n = tcol + 8 * i;
        size_t off = (size_t)(b0 + row) * DSTATE + n;
        g_Ct[off] = g_partC[0][off] + g_partC[1][off]
                  + g_partC[2][off] + g_partC[3][off];
    }
    __syncthreads();

    for (int o = t; o < 32 * 16; o += 256) {
        int r = o >> 4, n = o & 15;
        float acc = B_b2[n];
#pragma unroll
        for (int j = 0; j < 32; ++j) acc += Hs[r][j] * B_W2[n * 32 + j];
#pragma unroll
        for (int e = 0; e < 32; ++e) acc += Ev[(size_t)(b0 + r) * DEVENT + e] * B_We[n * 32 + e];
        g_Bt[(size_t)(b0 + r) * DSTATE + n] = acc;
    }
}

// ---------------- kernel 3: delta GEMM, cp.async double-buffered ----------
#define STG 4608  // 128*36 floats per operand per stage

__global__ __launch_bounds__(256) void k_gemm_delta(
    const float* __restrict__ X, const float* __restrict__ Wd,
    const float* __restrict__ Ev, const float* __restrict__ We,
    const float* __restrict__ bd) {
    extern __shared__ float smbuf[];
    float* As = smbuf;            // [2][128][36]
    float* Bs = smbuf + 2 * STG;  // [2][128][36]

    const int tid  = threadIdx.x;
    const int row0 = blockIdx.y * 128;   // batch
    const int col0 = blockIdx.x * 128;   // d_model
    const int wid  = tid >> 5, lane = tid & 31;
    const int g    = lane >> 2, tg = lane & 3;
    const int wm0  = (wid & 1) * 64;
    const int wn0  = (wid >> 1) * 32;

    float acc[4][4][4];
#pragma unroll
    for (int mi = 0; mi < 4; ++mi)
#pragma unroll
        for (int ni = 0; ni < 4; ++ni)
#pragma unroll
            for (int r = 0; r < 4; ++r) acc[mi][ni][r] = 0.0f;

    auto load_tile = [&](int kt, int s) {
        const float *srcA, *srcB;
        int lda, ldb;
        if (kt < 64) {
            srcA = X  + (size_t)row0 * DMODEL + kt * 32; lda = DMODEL;
            srcB = Wd + (size_t)col0 * DMODEL + kt * 32; ldb = DMODEL;
        } else {
            srcA = Ev + (size_t)row0 * DEVENT; lda = DEVENT;
            srcB = We + (size_t)col0 * DEVENT; ldb = DEVENT;
        }
        float* as = As + s * STG;
        float* bs = Bs + s * STG;
#pragma unroll
        for (int i = 0; i < 4; ++i) {
            int idx = tid + i * 256;     // 1024 16B chunks per operand
            int m = idx >> 3, k4 = idx & 7;
            cp16(as + m * 36 + k4 * 4, srcA + (size_t)m * lda + k4 * 4);
            cp16(bs + m * 36 + k4 * 4, srcB + (size_t)m * ldb + k4 * 4);
        }
    };

    load_tile(0, 0);
    cp_commit();

    for (int kt = 0; kt < 65; ++kt) {
        if (kt < 64) {
            load_tile(kt + 1, (kt + 1) & 1);
            cp_commit();
            asm volatile("cp.async.wait_group 1;\n");
        } else {
            asm volatile("cp.async.wait_group 0;\n");
        }
        __syncthreads();

        const float* as = As + (kt & 1) * STG;
        const float* bs = Bs + (kt & 1) * STG;
#pragma unroll
        for (int ks = 0; ks < 4; ++ks) {
            uint32_t a[4][4], b[4][2];
            int k = ks * 8 + tg;
#pragma unroll
            for (int mi = 0; mi < 4; ++mi) {
                int m = wm0 + mi * 16;
                a[mi][0] = __float_as_uint(as[(m + g) * 36 + k]);
                a[mi][1] = __float_as_uint(as[(m + g + 8) * 36 + k]);
                a[mi][2] = __float_as_uint(as[(m + g) * 36 + k + 4]);
                a[mi][3] = __float_as_uint(as[(m + g + 8) * 36 + k + 4]);
            }
#pragma unroll
            for (int ni = 0; ni < 4; ++ni) {
                int n = wn0 + ni * 8 + g;
                b[ni][0] = __float_as_uint(bs[n * 36 + k]);
                b[ni][1] = __float_as_uint(bs[n * 36 + k + 4]);
            }
#pragma unroll
            for (int mi = 0; mi < 4; ++mi)
#pragma unroll
                for (int ni = 0; ni < 4; ++ni)
                    mma_tf32(acc[mi][ni], a[mi], b[ni]);
        }
        __syncthreads();
    }

    // epilogue: delta_safe = min(softplus(z + bd), 2)
#pragma unroll
    for (int mi = 0; mi < 4; ++mi) {
        int rbase = row0 + wm0 + mi * 16 + g;
#pragma unroll
        for (int ni = 0; ni < 4; ++ni) {
            int cbase = col0 + wn0 + ni * 8 + tg * 2;
#pragma unroll
            for (int r = 0; r < 4; ++r) {
                int bb = rbase + (r >> 1) * 8;
                int dd = cbase + (r & 1);
                float z = acc[mi][ni][r] + __ldg(&bd[dd]);
                float sp = fmaxf(z, 0.0f) + __logf(1.0f + __expf(-fabsf(z)));
                g_delta[(size_t)bb * DMODEL + dd] = fminf(sp, 2.0f);
            }
        }
    }
}

// ---------------- kernel 4: state update (R1 4-lane layout) ---------------
__global__ __launch_bounds__(256) void k_state(
    const float* __restrict__ X, const float* __restrict__ Hprev,
    const float* __restrict__ Dv, float* __restrict__ Yout,
    float* __restrict__ Hout) {
    int tid  = blockIdx.x * 256 + threadIdx.x;
    int pair = tid >> 2;          // (b,d)
    int q    = tid & 3;           // state quarter
    int b    = pair >> 11;
    int d    = pair & 2047;

    float delta = g_delta[pair];
    float pole  = g_pole[pair];
    float xv    = X[pair];

    float4 hp = ((const float4*)Hprev)[(size_t)pair * 4 + q];
    float4 ab = ((const float4*)g_Abase)[d * 4 + q];
    float4 bt = ((const float4*)g_Bt)[b * 4 + q];
    float4 ct = ((const float4*)g_Ct)[b * 4 + q];

    float dbx = delta * xv;
    float4 h;
    h.x = __expf(delta * (ab.x + pole)) * hp.x + dbx * bt.x;
    h.y = __expf(delta * (ab.y + pole)) * hp.y + dbx * bt.y;
    h.z = __expf(delta * (ab.z + pole)) * hp.z + dbx * bt.z;
    h.w = __expf(delta * (ab.w + pole)) * hp.w + dbx * bt.w;

    ((float4*)Hout)[(size_t)pair * 4 + q] = h;

    float partial = h.x * ct.x + h.y * ct.y + h.z * ct.z + h.w * ct.w;
    partial += __shfl_xor_sync(0xffffffff, partial, 1);
    partial += __shfl_xor_sync(0xffffffff, partial, 2);
    if (q == 0) Yout[pair] = partial + Dv[d] * xv;
}

// ---------------- launch (serial, single stream) ----------------
extern "C" void kernel_launch(void* const* d_in, const int* in_sizes, int n_in,
                              void* d_out, int out_size) {
    const float* x      = (const float*)d_in[0];
    const float* h_prev = (const float*)d_in[1];
    const float* ev     = (const float*)d_in[2];
    const float* A_log  = (const float*)d_in[3];
    const float* Dv     = (const float*)d_in[4];
    const float* Wd     = (const float*)d_in[5];
    const float* bd     = (const float*)d_in[6];
    const float* We     = (const float*)d_in[7];
    const float* B_W1   = (const float*)d_in[8];
    const float* B_b1   = (const float*)d_in[9];
    const float* B_W2   = (const float*)d_in[10];
    const float* B_b2   = (const float*)d_in[11];
    const float* B_We   = (const float*)d_in[12];
    const float* A_We   = (const float*)d_in[13];
    const float* C_W    = (const float*)d_in[14];

    float* y_out = (float*)d_out;
    float* h_out = y_out + (size_t)BATCH * DMODEL;

    const int gemm_smem = 4 * STG * (int)sizeof(float);  // 73728 B
    cudaFuncSetAttribute(k_gemm_delta,
                         cudaFuncAttributeMaxDynamicSharedMemorySize, gemm_smem);

    k_pole<<<dim3(BATCH / 32, DMODEL / 128), 256>>>(ev, A_We, A_log);
    k_small_p<<<dim3(BATCH / 32, 4), 256>>>(x, B_W1, C_W);
    k_small_f<<<BATCH / 32, 256>>>(ev, B_b1, B_W2, B_b2, B_We);
    k_gemm_delta<<<dim3(DMODEL / 128, BATCH / 128), 256, gemm_smem>>>(
        x, Wd, ev, We, bd);
    k_state<<<(BATCH * DMODEL * 4) / 256, 256>>>(x, h_prev, Dv, y_out, h_out);
}